// round 5
// baseline (speedup 1.0000x reference)
#include <cuda_runtime.h>
#include <math.h>

#define S_LEN  512
#define BATCH  4
#define NHEAD  16
#define DHEAD  64
#define DMODEL 1024
#define D3     3072
#define NTOK   2048   // BATCH * S_LEN
#define QB     8

typedef unsigned long long u64;

// ---------------- f32x2 packed helpers (sm_100+) ----------------
__device__ __forceinline__ u64 fma2(u64 a, u64 b, u64 c) {
    u64 d;
    asm("fma.rn.f32x2 %0, %1, %2, %3;" : "=l"(d) : "l"(a), "l"(b), "l"(c));
    return d;
}
__device__ __forceinline__ u64 pack2(float lo, float hi) {
    u64 d;
    asm("mov.b64 %0, {%1, %2};" : "=l"(d)
        : "r"(__float_as_uint(lo)), "r"(__float_as_uint(hi)));
    return d;
}
__device__ __forceinline__ u64 dup2(float x) { return pack2(x, x); }
__device__ __forceinline__ u64 neg2(u64 a) { return a ^ 0x8000000080000000ull; }
__device__ __forceinline__ float lo2(u64 a) { return __uint_as_float((unsigned)(a & 0xffffffffull)); }
__device__ __forceinline__ float hi2(u64 a) { return __uint_as_float((unsigned)(a >> 32)); }

// ---------------- scratch (static device globals; no allocation) ----------------
__device__ float g_qkv_r[NTOK * D3];       // 25.2 MB
__device__ float g_qkv_i[NTOK * D3];
__device__ float g_attn_r[NTOK * DMODEL];  // 8.4 MB
__device__ float g_attn_i[NTOK * DMODEL];
__device__ float g_rc[S_LEN * DHEAD];
__device__ float g_rs[S_LEN * DHEAD];

// ---------------- RoPE rotor table ----------------
__global__ void rope_table_kernel() {
    int s = blockIdx.x, d = threadIdx.x;
    float inv = powf(10000.0f, -((float)d) / 64.0f);
    float ang = (float)s * inv;
    g_rc[s * DHEAD + d] = cosf(ang);
    g_rs[s * DHEAD + d] = sinf(ang);
}

// ---------------- complex GEMM: C = A * B^T (A:[M,K], B:[N,K], row-major) -------
// acc_r = Ar*Br - Ai*Bi ; acc_i = Ar*Bi + Ai*Br
// BM=128, BN=64, BK=16, 256 threads, 8x4 microtile, f32x2 packed along M.
__global__ __launch_bounds__(256)
void cgemm_nt_kernel(const float* __restrict__ Ar, const float* __restrict__ Ai,
                     const float* __restrict__ Br, const float* __restrict__ Bi,
                     float* __restrict__ Cr, float* __restrict__ Ci,
                     int N, int K)
{
    const int BM = 128, BN = 64, BK = 16;
    __shared__ alignas(16) float As_r[BK][BM];
    __shared__ alignas(16) float As_i[BK][BM];
    __shared__ alignas(16) float Bs_r[BK][BN];
    __shared__ alignas(16) float Bs_i[BK][BN];

    int tid = threadIdx.x;
    int tx = tid & 15;        // n-micro: cols tx*4 .. +3
    int ty = tid >> 4;        // m-micro: rows ty*8 .. +7
    int m0 = blockIdx.y * BM;
    int n0 = blockIdx.x * BN;

    int lrow = tid >> 1;          // 0..127 (A rows)
    int lk   = (tid & 1) * 8;     // 0 or 8
    int brow = tid >> 2;          // 0..63 (B rows)
    int bk   = (tid & 3) * 4;     // 0,4,8,12

    const float* pAr = Ar + (size_t)(m0 + lrow) * K + lk;
    const float* pAi = Ai + (size_t)(m0 + lrow) * K + lk;
    const float* pBr = Br + (size_t)(n0 + brow) * K + bk;
    const float* pBi = Bi + (size_t)(n0 + brow) * K + bk;

    u64 acc_r[4][4], acc_i[4][4];
#pragma unroll
    for (int i = 0; i < 4; i++)
#pragma unroll
        for (int j = 0; j < 4; j++) { acc_r[i][j] = 0ull; acc_i[i][j] = 0ull; }

    for (int k0 = 0; k0 < K; k0 += BK) {
        // issue global loads early (overlap previous tile's compute)
        float4 ar0 = *(const float4*)(pAr + k0);
        float4 ar1 = *(const float4*)(pAr + k0 + 4);
        float4 ai0 = *(const float4*)(pAi + k0);
        float4 ai1 = *(const float4*)(pAi + k0 + 4);
        float4 br0 = *(const float4*)(pBr + k0);
        float4 bi0 = *(const float4*)(pBi + k0);

        __syncthreads();   // previous tile's compute done
#pragma unroll
        for (int j = 0; j < 4; j++) {
            As_r[lk + j][lrow]     = (&ar0.x)[j];
            As_r[lk + 4 + j][lrow] = (&ar1.x)[j];
            As_i[lk + j][lrow]     = (&ai0.x)[j];
            As_i[lk + 4 + j][lrow] = (&ai1.x)[j];
            Bs_r[bk + j][brow]     = (&br0.x)[j];
            Bs_i[bk + j][brow]     = (&bi0.x)[j];
        }
        __syncthreads();

#pragma unroll
        for (int kk = 0; kk < BK; kk++) {
            ulonglong2 xr01 = *(const ulonglong2*)(&As_r[kk][ty * 8]);
            ulonglong2 xr23 = *(const ulonglong2*)(&As_r[kk][ty * 8 + 4]);
            ulonglong2 xi01 = *(const ulonglong2*)(&As_i[kk][ty * 8]);
            ulonglong2 xi23 = *(const ulonglong2*)(&As_i[kk][ty * 8 + 4]);
            u64 xr2[4]  = {xr01.x, xr01.y, xr23.x, xr23.y};
            u64 xi2[4]  = {xi01.x, xi01.y, xi23.x, xi23.y};
            u64 nxi2[4] = {neg2(xi01.x), neg2(xi01.y), neg2(xi23.x), neg2(xi23.y)};

            float4 yr4 = *(const float4*)(&Bs_r[kk][tx * 4]);
            float4 yi4 = *(const float4*)(&Bs_i[kk][tx * 4]);
            u64 yr2[4], yi2[4];
#pragma unroll
            for (int j = 0; j < 4; j++) {
                yr2[j] = dup2((&yr4.x)[j]);
                yi2[j] = dup2((&yi4.x)[j]);
            }
#pragma unroll
            for (int ip = 0; ip < 4; ip++)
#pragma unroll
                for (int j = 0; j < 4; j++) {
                    acc_r[ip][j] = fma2(xr2[ip],  yr2[j], acc_r[ip][j]);
                    acc_r[ip][j] = fma2(nxi2[ip], yi2[j], acc_r[ip][j]);
                    acc_i[ip][j] = fma2(xr2[ip],  yi2[j], acc_i[ip][j]);
                    acc_i[ip][j] = fma2(xi2[ip],  yr2[j], acc_i[ip][j]);
                }
        }
    }

    // epilogue: unpack M-pairs, vector stores
#pragma unroll
    for (int ip = 0; ip < 4; ip++) {
        int m_lo = m0 + ty * 8 + 2 * ip;
        float4 vr_lo, vr_hi, vi_lo, vi_hi;
#pragma unroll
        for (int j = 0; j < 4; j++) {
            (&vr_lo.x)[j] = lo2(acc_r[ip][j]);
            (&vr_hi.x)[j] = hi2(acc_r[ip][j]);
            (&vi_lo.x)[j] = lo2(acc_i[ip][j]);
            (&vi_hi.x)[j] = hi2(acc_i[ip][j]);
        }
        size_t c0 = (size_t)m_lo * N + n0 + tx * 4;
        *(float4*)(Cr + c0)     = vr_lo;
        *(float4*)(Cr + c0 + N) = vr_hi;
        *(float4*)(Ci + c0)     = vi_lo;
        *(float4*)(Ci + c0 + N) = vi_hi;
    }
}

// ---------------- in-place RoPE on Q,K columns of qkv ----------------
__global__ __launch_bounds__(256)
void rope_apply_kernel(float* __restrict__ qr, float* __restrict__ qi) {
    int t = blockIdx.x;          // token 0..2047
    int s = t & (S_LEN - 1);
    size_t base = (size_t)t * D3;
    for (int c = threadIdx.x; c < 2 * DMODEL; c += 256) {
        int d = c & (DHEAD - 1);
        float co = g_rc[s * DHEAD + d];
        float si = g_rs[s * DHEAD + d];
        float xr = qr[base + c];
        float xi = qi[base + c];
        qr[base + c] = xr * co - xi * si;
        qi[base + c] = xr * si + xi * co;
    }
}

// ---------------- fused attention: one block per (b, h, 8-q tile) ----------------
__global__ __launch_bounds__(256)
void attn_kernel(const float* __restrict__ qkv_r, const float* __restrict__ qkv_i,
                 float* __restrict__ out_r, float* __restrict__ out_i)
{
    __shared__ alignas(16) float sQr[QB][64];
    __shared__ alignas(16) float sQi[QB][64];
    __shared__ alignas(16) float sWc[QB][S_LEN]; // re score -> exp -> p*cos
    __shared__ alignas(16) float sWs[QB][S_LEN]; // im score -> p*sin

    int tid = threadIdx.x;
    int h = blockIdx.y, b = blockIdx.z;
    int q0 = blockIdx.x * QB;
    const size_t tok_base = (size_t)b * S_LEN;

    // ---- load 8 rotated Q rows ----
    for (int idx = tid; idx < QB * 64; idx += 256) {
        int q = idx >> 6, d = idx & 63;
        size_t off = (tok_base + q0 + q) * D3 + (size_t)h * DHEAD + d;
        sQr[q][d] = qkv_r[off];
        sQi[q][d] = qkv_i[off];
    }
    __syncthreads();

    // ---- scores: thread t handles k rows t and t+256, all 8 q ----
    const float scale = 0.125f;  // 1/sqrt(64)
#pragma unroll
    for (int rep = 0; rep < 2; rep++) {
        int k = tid + rep * 256;
        const float* pkr = qkv_r + (tok_base + k) * D3 + DMODEL + h * DHEAD;
        const float* pki = qkv_i + (tok_base + k) * D3 + DMODEL + h * DHEAD;
        u64 re2[QB], im2[QB];
#pragma unroll
        for (int q = 0; q < QB; q++) { re2[q] = 0ull; im2[q] = 0ull; }
#pragma unroll
        for (int c = 0; c < 16; c++) {
            ulonglong2 kr = *(const ulonglong2*)(pkr + c * 4);
            ulonglong2 ki = *(const ulonglong2*)(pki + c * 4);
#pragma unroll
            for (int q = 0; q < QB; q++) {
                u64 qra = *(const u64*)(&sQr[q][c * 4]);
                u64 qrb = *(const u64*)(&sQr[q][c * 4 + 2]);
                u64 qia = *(const u64*)(&sQi[q][c * 4]);
                u64 qib = *(const u64*)(&sQi[q][c * 4 + 2]);
                re2[q] = fma2(qra, kr.x, re2[q]);
                re2[q] = fma2(qrb, kr.y, re2[q]);
                re2[q] = fma2(qia, ki.x, re2[q]);
                re2[q] = fma2(qib, ki.y, re2[q]);
                im2[q] = fma2(qia, kr.x, im2[q]);
                im2[q] = fma2(qib, kr.y, im2[q]);
                im2[q] = fma2(neg2(qra), ki.x, im2[q]);
                im2[q] = fma2(neg2(qrb), ki.y, im2[q]);
            }
        }
#pragma unroll
        for (int q = 0; q < QB; q++) {
            sWc[q][k] = (lo2(re2[q]) + hi2(re2[q])) * scale;
            sWs[q][k] = (lo2(im2[q]) + hi2(im2[q])) * scale;
        }
    }
    __syncthreads();

    // ---- softmax + complex weights: warp w owns q-row w ----
    int w = tid >> 5, l = tid & 31;
    {
        float mx = -1e30f;
#pragma unroll
        for (int j = 0; j < 16; j++) mx = fmaxf(mx, sWc[w][l + 32 * j]);
#pragma unroll
        for (int o = 16; o > 0; o >>= 1)
            mx = fmaxf(mx, __shfl_xor_sync(0xffffffff, mx, o));

        float sum = 0.f;
#pragma unroll
        for (int j = 0; j < 16; j++) {
            int idx = l + 32 * j;
            float e = __expf(sWc[w][idx] - mx);
            sWc[w][idx] = e;
            sum += e;
        }
#pragma unroll
        for (int o = 16; o > 0; o >>= 1)
            sum += __shfl_xor_sync(0xffffffff, sum, o);
        float inv = 1.0f / sum;

#pragma unroll
        for (int j = 0; j < 16; j++) {
            int idx = l + 32 * j;
            float p = sWc[w][idx] * inv;
            float sv, cv;
            sincosf(sWs[w][idx], &sv, &cv);
            sWc[w][idx] = p * cv;
            sWs[w][idx] = p * sv;
        }
    }
    __syncthreads();

    // ---- AV: warp w -> q-row w; lane l -> dims (2l, 2l+1) ----
    const float* pvr = qkv_r + tok_base * D3 + 2 * DMODEL + h * DHEAD + 2 * l;
    const float* pvi = qkv_i + tok_base * D3 + 2 * DMODEL + h * DHEAD + 2 * l;
    u64 aA = 0ull, aB = 0ull, aC = 0ull, aD = 0ull;
#pragma unroll 4
    for (int k = 0; k < S_LEN; k++) {
        u64 wc2 = dup2(sWc[w][k]);
        u64 ws2 = dup2(sWs[w][k]);
        u64 vr = *(const u64*)(pvr + (size_t)k * D3);
        u64 vi = *(const u64*)(pvi + (size_t)k * D3);
        aA = fma2(wc2, vr, aA);   // sum wc*Vr
        aB = fma2(ws2, vi, aB);   // sum ws*Vi
        aC = fma2(wc2, vi, aC);   // sum wc*Vi
        aD = fma2(ws2, vr, aD);   // sum ws*Vr
    }
    size_t o = (tok_base + q0 + w) * DMODEL + (size_t)h * DHEAD + 2 * l;
    float2 vr_out = make_float2(lo2(aA) - lo2(aB), hi2(aA) - hi2(aB));
    float2 vi_out = make_float2(lo2(aC) + lo2(aD), hi2(aC) + hi2(aD));
    *(float2*)(out_r + o) = vr_out;
    *(float2*)(out_i + o) = vi_out;
}

// ---------------- launch ----------------
extern "C" void kernel_launch(void* const* d_in, const int* in_sizes, int n_in,
                              void* d_out, int out_size)
{
    const float* x_re    = (const float*)d_in[0];
    const float* x_im    = (const float*)d_in[1];
    const float* wqkv_re = (const float*)d_in[2];
    const float* wqkv_im = (const float*)d_in[3];
    const float* wo_re   = (const float*)d_in[4];
    const float* wo_im   = (const float*)d_in[5];
    float* out = (float*)d_out;

    float *qkv_r, *qkv_i, *attn_r, *attn_i;
    cudaGetSymbolAddress((void**)&qkv_r,  g_qkv_r);
    cudaGetSymbolAddress((void**)&qkv_i,  g_qkv_i);
    cudaGetSymbolAddress((void**)&attn_r, g_attn_r);
    cudaGetSymbolAddress((void**)&attn_i, g_attn_i);

    // 1. RoPE rotor table
    rope_table_kernel<<<S_LEN, DHEAD>>>();

    // 2. complex QKV projection: [2048,1024] x [3072,1024]^T
    dim3 g1(D3 / 64, NTOK / 128);
    cgemm_nt_kernel<<<g1, 256>>>(x_re, x_im, wqkv_re, wqkv_im, qkv_r, qkv_i, D3, DMODEL);

    // 3. RoPE applied in place to Q and K columns
    rope_apply_kernel<<<NTOK, 256>>>(qkv_r, qkv_i);

    // 4. fused attention, 8 q-rows per block
    dim3 g2(S_LEN / QB, NHEAD, BATCH);
    attn_kernel<<<g2, 256>>>(qkv_r, qkv_i, attn_r, attn_i);

    // 5. complex output projection straight into d_out ([2,B,S,D])
    dim3 g3(DMODEL / 64, NTOK / 128);
    cgemm_nt_kernel<<<g3, 256>>>(attn_r, attn_i, wo_re, wo_im,
                                 out, out + (size_t)NTOK * DMODEL, DMODEL, DMODEL);
}

// round 6
// speedup vs baseline: 3.4030x; 3.4030x over previous
#include <cuda_runtime.h>
#include <math.h>

#define S_LEN  512
#define BATCH  4
#define NHEAD  16
#define DHEAD  64
#define DMODEL 1024
#define D3     3072
#define NTOK   2048   // BATCH * S_LEN
#define QB     8

typedef unsigned long long u64;

// ---------------- f32x2 packed helpers (sm_100+) ----------------
__device__ __forceinline__ u64 fma2(u64 a, u64 b, u64 c) {
    u64 d;
    asm("fma.rn.f32x2 %0, %1, %2, %3;" : "=l"(d) : "l"(a), "l"(b), "l"(c));
    return d;
}
__device__ __forceinline__ u64 pack2(float lo, float hi) {
    u64 d;
    asm("mov.b64 %0, {%1, %2};" : "=l"(d)
        : "r"(__float_as_uint(lo)), "r"(__float_as_uint(hi)));
    return d;
}
__device__ __forceinline__ u64 dup2(float x) { return pack2(x, x); }
__device__ __forceinline__ u64 neg2(u64 a) { return a ^ 0x8000000080000000ull; }
__device__ __forceinline__ float lo2(u64 a) { return __uint_as_float((unsigned)(a & 0xffffffffull)); }
__device__ __forceinline__ float hi2(u64 a) { return __uint_as_float((unsigned)(a >> 32)); }

// ---------------- tf32 helpers ----------------
__device__ __forceinline__ unsigned f2tf32(float x) {
    unsigned r;
    asm("cvt.rna.tf32.f32 %0, %1;" : "=r"(r) : "f"(x));
    return r;
}
__device__ __forceinline__ void mma_tf32(float* c, const unsigned* a, const unsigned* b) {
    asm volatile("mma.sync.aligned.m16n8k8.row.col.f32.tf32.tf32.f32 "
        "{%0,%1,%2,%3}, {%4,%5,%6,%7}, {%8,%9}, {%0,%1,%2,%3};"
        : "+f"(c[0]), "+f"(c[1]), "+f"(c[2]), "+f"(c[3])
        : "r"(a[0]), "r"(a[1]), "r"(a[2]), "r"(a[3]), "r"(b[0]), "r"(b[1]));
}

// ---------------- scratch (static device globals; no allocation) ----------------
__device__ float g_qkv_r[NTOK * D3];       // 25.2 MB
__device__ float g_qkv_i[NTOK * D3];
__device__ float g_kt_r[BATCH * NHEAD * DHEAD * S_LEN];  // 8.4 MB (rotated K, [b,h,d,s])
__device__ float g_kt_i[BATCH * NHEAD * DHEAD * S_LEN];
__device__ float g_attn_r[NTOK * DMODEL];  // 8.4 MB
__device__ float g_attn_i[NTOK * DMODEL];
__device__ float g_rc[S_LEN * DHEAD];
__device__ float g_rs[S_LEN * DHEAD];

// ---------------- RoPE rotor table ----------------
__global__ void rope_table_kernel() {
    int s = blockIdx.x, d = threadIdx.x;
    float inv = powf(10000.0f, -((float)d) / 64.0f);
    float ang = (float)s * inv;
    g_rc[s * DHEAD + d] = cosf(ang);
    g_rs[s * DHEAD + d] = sinf(ang);
}

// ============ complex GEMM via tf32 tensor-core mma: C = A * B^T ============
// A:[M,K], B:[N,K] row-major.  re = Ar*Br - Ai*Bi ; im = Ar*Bi + Ai*Br.
// Block 128 thr (4 warps, 2x2), tile 64x64, BK=16. smem holds tf32 bits
// with a pre-negated Bi copy so only 2 accumulator chains are needed.
#define SST 20   // smem row stride (words): conflict-free frags, 16B-aligned stores
__global__ __launch_bounds__(128)
void cgemm_mma_kernel(const float* __restrict__ Ar, const float* __restrict__ Ai,
                      const float* __restrict__ Br, const float* __restrict__ Bi,
                      float* __restrict__ Cr, float* __restrict__ Ci,
                      int N, int K)
{
    __shared__ unsigned sAr[64 * SST], sAi[64 * SST];
    __shared__ unsigned sBr[64 * SST], sBi[64 * SST], sBn[64 * SST];

    int tid  = threadIdx.x;
    int lane = tid & 31, warp = tid >> 5;
    int wm = (warp & 1) * 32;   // warp m-offset in tile
    int wn = (warp >> 1) * 32;  // warp n-offset
    int g = lane >> 2, t = lane & 3;
    int m0 = blockIdx.y * 64;
    int n0 = blockIdx.x * 64;

    // loader: thread covers rows (tid>>2) and (tid>>2)+32, cols (tid&3)*4..+3
    int lrow = tid >> 2;
    int lcol = (tid & 3) * 4;
    const float* pa_r = Ar + (size_t)(m0 + lrow) * K + lcol;
    const float* pa_i = Ai + (size_t)(m0 + lrow) * K + lcol;
    const float* pb_r = Br + (size_t)(n0 + lrow) * K + lcol;
    const float* pb_i = Bi + (size_t)(n0 + lrow) * K + lcol;
    size_t rstep = (size_t)32 * K;

    float acc_r[8][4], acc_i[8][4];
#pragma unroll
    for (int p = 0; p < 8; p++)
#pragma unroll
        for (int j = 0; j < 4; j++) { acc_r[p][j] = 0.f; acc_i[p][j] = 0.f; }

    for (int k0 = 0; k0 < K; k0 += 16) {
        // global loads issued early
        float4 ar0 = *(const float4*)(pa_r + k0);
        float4 ar1 = *(const float4*)(pa_r + rstep + k0);
        float4 ai0 = *(const float4*)(pa_i + k0);
        float4 ai1 = *(const float4*)(pa_i + rstep + k0);
        float4 br0 = *(const float4*)(pb_r + k0);
        float4 br1 = *(const float4*)(pb_r + rstep + k0);
        float4 bi0 = *(const float4*)(pb_i + k0);
        float4 bi1 = *(const float4*)(pb_i + rstep + k0);

        __syncthreads();  // previous iter's frag reads done

        uint4 u;
        int o0 = lrow * SST + lcol;
        int o1 = (lrow + 32) * SST + lcol;
        u = make_uint4(f2tf32(ar0.x), f2tf32(ar0.y), f2tf32(ar0.z), f2tf32(ar0.w));
        *(uint4*)(sAr + o0) = u;
        u = make_uint4(f2tf32(ar1.x), f2tf32(ar1.y), f2tf32(ar1.z), f2tf32(ar1.w));
        *(uint4*)(sAr + o1) = u;
        u = make_uint4(f2tf32(ai0.x), f2tf32(ai0.y), f2tf32(ai0.z), f2tf32(ai0.w));
        *(uint4*)(sAi + o0) = u;
        u = make_uint4(f2tf32(ai1.x), f2tf32(ai1.y), f2tf32(ai1.z), f2tf32(ai1.w));
        *(uint4*)(sAi + o1) = u;
        u = make_uint4(f2tf32(br0.x), f2tf32(br0.y), f2tf32(br0.z), f2tf32(br0.w));
        *(uint4*)(sBr + o0) = u;
        u = make_uint4(f2tf32(br1.x), f2tf32(br1.y), f2tf32(br1.z), f2tf32(br1.w));
        *(uint4*)(sBr + o1) = u;
        u = make_uint4(f2tf32(bi0.x), f2tf32(bi0.y), f2tf32(bi0.z), f2tf32(bi0.w));
        *(uint4*)(sBi + o0) = u;
        u = make_uint4(f2tf32(-bi0.x), f2tf32(-bi0.y), f2tf32(-bi0.z), f2tf32(-bi0.w));
        *(uint4*)(sBn + o0) = u;
        u = make_uint4(f2tf32(bi1.x), f2tf32(bi1.y), f2tf32(bi1.z), f2tf32(bi1.w));
        *(uint4*)(sBi + o1) = u;
        u = make_uint4(f2tf32(-bi1.x), f2tf32(-bi1.y), f2tf32(-bi1.z), f2tf32(-bi1.w));
        *(uint4*)(sBn + o1) = u;

        __syncthreads();

#pragma unroll
        for (int k8 = 0; k8 < 16; k8 += 8) {
            unsigned fAr[2][4], fAi[2][4];
#pragma unroll
            for (int mt = 0; mt < 2; mt++) {
                int r0 = (wm + mt * 16 + g) * SST + k8 + t;
                int r1 = (wm + mt * 16 + g + 8) * SST + k8 + t;
                fAr[mt][0] = sAr[r0];     fAr[mt][1] = sAr[r1];
                fAr[mt][2] = sAr[r0 + 4]; fAr[mt][3] = sAr[r1 + 4];
                fAi[mt][0] = sAi[r0];     fAi[mt][1] = sAi[r1];
                fAi[mt][2] = sAi[r0 + 4]; fAi[mt][3] = sAi[r1 + 4];
            }
            unsigned fBr[4][2], fBi[4][2], fBn[4][2];
#pragma unroll
            for (int nt = 0; nt < 4; nt++) {
                int rb = (wn + nt * 8 + g) * SST + k8 + t;
                fBr[nt][0] = sBr[rb]; fBr[nt][1] = sBr[rb + 4];
                fBi[nt][0] = sBi[rb]; fBi[nt][1] = sBi[rb + 4];
                fBn[nt][0] = sBn[rb]; fBn[nt][1] = sBn[rb + 4];
            }
#pragma unroll
            for (int mt = 0; mt < 2; mt++)
#pragma unroll
                for (int nt = 0; nt < 4; nt++) {
                    int p = mt * 4 + nt;
                    mma_tf32(acc_r[p], fAr[mt], fBr[nt]);  // + Ar*Br
                    mma_tf32(acc_r[p], fAi[mt], fBn[nt]);  // - Ai*Bi
                    mma_tf32(acc_i[p], fAr[mt], fBi[nt]);  // + Ar*Bi
                    mma_tf32(acc_i[p], fAi[mt], fBr[nt]);  // + Ai*Br
                }
        }
    }

    // epilogue
#pragma unroll
    for (int mt = 0; mt < 2; mt++)
#pragma unroll
        for (int nt = 0; nt < 4; nt++) {
            int p = mt * 4 + nt;
            int m = m0 + wm + mt * 16 + g;
            int n = n0 + wn + nt * 8 + t * 2;
            size_t c0 = (size_t)m * N + n;
            size_t c1 = (size_t)(m + 8) * N + n;
            *(float2*)(Cr + c0) = make_float2(acc_r[p][0], acc_r[p][1]);
            *(float2*)(Cr + c1) = make_float2(acc_r[p][2], acc_r[p][3]);
            *(float2*)(Ci + c0) = make_float2(acc_i[p][0], acc_i[p][1]);
            *(float2*)(Ci + c1) = make_float2(acc_i[p][2], acc_i[p][3]);
        }
}

// ---------- K: rotate + transpose into Kt[b,h,d,s] (coalesced both sides) ------
__global__ __launch_bounds__(256)
void kpack_kernel(const float* __restrict__ qkv_r, const float* __restrict__ qkv_i,
                  float* __restrict__ kt_r, float* __restrict__ kt_i)
{
    __shared__ float Tr[32][33], Ti[32][33];
    int s0 = blockIdx.x * 32;
    int h  = blockIdx.y >> 1;
    int d0 = (blockIdx.y & 1) * 32;
    int b  = blockIdx.z;
    int tid = threadIdx.x;
    int tx = tid & 31, ty = tid >> 5;
    size_t tok = (size_t)b * S_LEN;

#pragma unroll
    for (int r = 0; r < 4; r++) {
        int sl = ty + r * 8;
        int s = s0 + sl;
        int d = d0 + tx;
        size_t off = (tok + s) * D3 + DMODEL + (size_t)h * DHEAD + d;
        float kr = qkv_r[off], ki = qkv_i[off];
        float co = g_rc[s * DHEAD + d], si = g_rs[s * DHEAD + d];
        Tr[sl][tx] = kr * co - ki * si;
        Ti[sl][tx] = kr * si + ki * co;
    }
    __syncthreads();

    size_t base = ((size_t)(b * NHEAD + h) * DHEAD + d0) * S_LEN + s0;
#pragma unroll
    for (int r = 0; r < 4; r++) {
        int dl = ty + r * 8;
        kt_r[base + (size_t)dl * S_LEN + tx] = Tr[tx][dl];
        kt_i[base + (size_t)dl * S_LEN + tx] = Ti[tx][dl];
    }
}

// ---------------- fused attention: one block per (b, h, 8-q tile) ----------------
__global__ __launch_bounds__(256)
void attn_kernel(const float* __restrict__ qkv_r, const float* __restrict__ qkv_i,
                 const float* __restrict__ kt_r, const float* __restrict__ kt_i,
                 float* __restrict__ out_r, float* __restrict__ out_i)
{
    __shared__ u64 sQr2[QB][DHEAD];              // dup'd rotated Q
    __shared__ u64 sQi2[QB][DHEAD];
    __shared__ alignas(16) float sWc[QB][S_LEN]; // re score -> exp -> p*cos
    __shared__ alignas(16) float sWs[QB][S_LEN]; // im score -> p*sin

    int tid = threadIdx.x;
    int h = blockIdx.y, b = blockIdx.z;
    int q0 = blockIdx.x * QB;
    const size_t tok_base = (size_t)b * S_LEN;

    // ---- load + rotate 8 Q rows, store pre-dup'd ----
    for (int idx = tid; idx < QB * DHEAD; idx += 256) {
        int q = idx >> 6, d = idx & 63;
        int s = q0 + q;
        size_t off = (tok_base + s) * D3 + (size_t)h * DHEAD + d;
        float qr = qkv_r[off], qi = qkv_i[off];
        float co = g_rc[s * DHEAD + d], si = g_rs[s * DHEAD + d];
        sQr2[q][d] = dup2(qr * co - qi * si);
        sQi2[q][d] = dup2(qr * si + qi * co);
    }
    __syncthreads();

    // ---- scores: thread t handles k-pair (2t, 2t+1) for all 8 q ----
    const float scale = 0.125f;  // 1/sqrt(64)
    {
        size_t kt_base = (size_t)(b * NHEAD + h) * DHEAD * S_LEN + 2 * tid;
        const float* pkr = kt_r + kt_base;
        const float* pki = kt_i + kt_base;
        u64 re2[QB], im2[QB];
#pragma unroll
        for (int q = 0; q < QB; q++) { re2[q] = 0ull; im2[q] = 0ull; }
#pragma unroll 4
        for (int d = 0; d < DHEAD; d++) {
            u64 kr = *(const u64*)(pkr + (size_t)d * S_LEN);
            u64 ki = *(const u64*)(pki + (size_t)d * S_LEN);
#pragma unroll
            for (int q = 0; q < QB; q++) {
                u64 qr2 = sQr2[q][d];
                u64 qi2 = sQi2[q][d];
                re2[q] = fma2(qr2, kr, re2[q]);       // + Qr*Kr
                re2[q] = fma2(qi2, ki, re2[q]);       // + Qi*Ki
                im2[q] = fma2(qi2, kr, im2[q]);       // + Qi*Kr
                im2[q] = fma2(neg2(qr2), ki, im2[q]); // - Qr*Ki
            }
        }
#pragma unroll
        for (int q = 0; q < QB; q++) {
            *(float2*)&sWc[q][2 * tid] = make_float2(lo2(re2[q]) * scale, hi2(re2[q]) * scale);
            *(float2*)&sWs[q][2 * tid] = make_float2(lo2(im2[q]) * scale, hi2(im2[q]) * scale);
        }
    }
    __syncthreads();

    // ---- softmax + complex weights: warp w owns q-row w ----
    int w = tid >> 5, l = tid & 31;
    {
        float mx = -1e30f;
#pragma unroll
        for (int j = 0; j < 16; j++) mx = fmaxf(mx, sWc[w][l + 32 * j]);
#pragma unroll
        for (int o = 16; o > 0; o >>= 1)
            mx = fmaxf(mx, __shfl_xor_sync(0xffffffff, mx, o));

        float sum = 0.f;
#pragma unroll
        for (int j = 0; j < 16; j++) {
            int idx = l + 32 * j;
            float e = __expf(sWc[w][idx] - mx);
            sWc[w][idx] = e;
            sum += e;
        }
#pragma unroll
        for (int o = 16; o > 0; o >>= 1)
            sum += __shfl_xor_sync(0xffffffff, sum, o);
        float inv = 1.0f / sum;

#pragma unroll
        for (int j = 0; j < 16; j++) {
            int idx = l + 32 * j;
            float p = sWc[w][idx] * inv;
            float sv, cv;
            sincosf(sWs[w][idx], &sv, &cv);
            sWc[w][idx] = p * cv;
            sWs[w][idx] = p * sv;
        }
    }
    __syncthreads();

    // ---- AV: warp w -> q-row w; lane l -> dims (2l, 2l+1) ----
    const float* pvr = qkv_r + tok_base * D3 + 2 * DMODEL + (size_t)h * DHEAD + 2 * l;
    const float* pvi = qkv_i + tok_base * D3 + 2 * DMODEL + (size_t)h * DHEAD + 2 * l;
    u64 aA = 0ull, aB = 0ull, aC = 0ull, aD = 0ull;
#pragma unroll 4
    for (int k = 0; k < S_LEN; k++) {
        u64 wc2 = dup2(sWc[w][k]);
        u64 ws2 = dup2(sWs[w][k]);
        u64 vr = *(const u64*)(pvr + (size_t)k * D3);
        u64 vi = *(const u64*)(pvi + (size_t)k * D3);
        aA = fma2(wc2, vr, aA);   // sum wc*Vr
        aB = fma2(ws2, vi, aB);   // sum ws*Vi
        aC = fma2(wc2, vi, aC);   // sum wc*Vi
        aD = fma2(ws2, vr, aD);   // sum ws*Vr
    }
    size_t o = (tok_base + q0 + w) * DMODEL + (size_t)h * DHEAD + 2 * l;
    *(float2*)(out_r + o) = make_float2(lo2(aA) - lo2(aB), hi2(aA) - hi2(aB));
    *(float2*)(out_i + o) = make_float2(lo2(aC) + lo2(aD), hi2(aC) + hi2(aD));
}

// ---------------- launch ----------------
extern "C" void kernel_launch(void* const* d_in, const int* in_sizes, int n_in,
                              void* d_out, int out_size)
{
    const float* x_re    = (const float*)d_in[0];
    const float* x_im    = (const float*)d_in[1];
    const float* wqkv_re = (const float*)d_in[2];
    const float* wqkv_im = (const float*)d_in[3];
    const float* wo_re   = (const float*)d_in[4];
    const float* wo_im   = (const float*)d_in[5];
    float* out = (float*)d_out;

    float *qkv_r, *qkv_i, *kt_r, *kt_i, *attn_r, *attn_i;
    cudaGetSymbolAddress((void**)&qkv_r,  g_qkv_r);
    cudaGetSymbolAddress((void**)&qkv_i,  g_qkv_i);
    cudaGetSymbolAddress((void**)&kt_r,   g_kt_r);
    cudaGetSymbolAddress((void**)&kt_i,   g_kt_i);
    cudaGetSymbolAddress((void**)&attn_r, g_attn_r);
    cudaGetSymbolAddress((void**)&attn_i, g_attn_i);

    // 1. RoPE rotor table
    rope_table_kernel<<<S_LEN, DHEAD>>>();

    // 2. complex QKV projection: [2048,1024] x [3072,1024]^T  (tf32 tensor cores)
    dim3 g1(D3 / 64, NTOK / 64);
    cgemm_mma_kernel<<<g1, 128>>>(x_re, x_im, wqkv_re, wqkv_im, qkv_r, qkv_i, D3, DMODEL);

    // 3. K: rotate + transpose into [b,h,d,s]
    dim3 g2(S_LEN / 32, NHEAD * 2, BATCH);
    kpack_kernel<<<g2, 256>>>(qkv_r, qkv_i, kt_r, kt_i);

    // 4. fused attention, 8 q-rows per block (Q rotated on load)
    dim3 g3(S_LEN / QB, NHEAD, BATCH);
    attn_kernel<<<g3, 256>>>(qkv_r, qkv_i, kt_r, kt_i, attn_r, attn_i);

    // 5. complex output projection straight into d_out ([2,B,S,D])
    dim3 g4(DMODEL / 64, NTOK / 64);
    cgemm_mma_kernel<<<g4, 128>>>(attn_r, attn_i, wo_re, wo_im,
                                  out, out + (size_t)NTOK * DMODEL, DMODEL, DMODEL);
}

// round 8
// speedup vs baseline: 4.0181x; 1.1808x over previous
#include <cuda_runtime.h>
#include <cuda_bf16.h>
#include <math.h>

#define S_LEN  512
#define BATCH  4
#define NHEAD  16
#define DHEAD  64
#define DMODEL 1024
#define D3     3072
#define NTOK   2048   // BATCH * S_LEN
#define QB     16

typedef unsigned long long u64;

// ---------------- f32x2 packed helpers (sm_100+) ----------------
__device__ __forceinline__ u64 fma2(u64 a, u64 b, u64 c) {
    u64 d;
    asm("fma.rn.f32x2 %0, %1, %2, %3;" : "=l"(d) : "l"(a), "l"(b), "l"(c));
    return d;
}
__device__ __forceinline__ u64 pack2(float lo, float hi) {
    u64 d;
    asm("mov.b64 %0, {%1, %2};" : "=l"(d)
        : "r"(__float_as_uint(lo)), "r"(__float_as_uint(hi)));
    return d;
}
__device__ __forceinline__ u64 dup2(float x) { return pack2(x, x); }
__device__ __forceinline__ u64 neg2(u64 a) { return a ^ 0x8000000080000000ull; }
__device__ __forceinline__ float lo2(u64 a) { return __uint_as_float((unsigned)(a & 0xffffffffull)); }
__device__ __forceinline__ float hi2(u64 a) { return __uint_as_float((unsigned)(a >> 32)); }

// ---------------- bf16 mma helper ----------------
__device__ __forceinline__ void mma_bf16(float* c, const unsigned* a, const unsigned* b) {
    asm volatile("mma.sync.aligned.m16n8k16.row.col.f32.bf16.bf16.f32 "
        "{%0,%1,%2,%3}, {%4,%5,%6,%7}, {%8,%9}, {%0,%1,%2,%3};"
        : "+f"(c[0]), "+f"(c[1]), "+f"(c[2]), "+f"(c[3])
        : "r"(a[0]), "r"(a[1]), "r"(a[2]), "r"(a[3]), "r"(b[0]), "r"(b[1]));
}

// split 8 consecutive floats into bf16-hi / bf16-lo pair-packed words
__device__ __forceinline__ void split8(const float4& x, const float4& y,
                                       uint4& hi, uint4& lo) {
    const float* v0 = &x.x;
    const float* v1 = &y.x;
    unsigned h[4], l[4];
#pragma unroll
    for (int j = 0; j < 2; j++) {
        float a = v0[2 * j], b = v0[2 * j + 1];
        __nv_bfloat162 H = __floats2bfloat162_rn(a, b);
        float la = a - __bfloat162float(H.x);
        float lb = b - __bfloat162float(H.y);
        __nv_bfloat162 L = __floats2bfloat162_rn(la, lb);
        h[j] = *(unsigned*)&H;
        l[j] = *(unsigned*)&L;
    }
#pragma unroll
    for (int j = 0; j < 2; j++) {
        float a = v1[2 * j], b = v1[2 * j + 1];
        __nv_bfloat162 H = __floats2bfloat162_rn(a, b);
        float la = a - __bfloat162float(H.x);
        float lb = b - __bfloat162float(H.y);
        __nv_bfloat162 L = __floats2bfloat162_rn(la, lb);
        h[2 + j] = *(unsigned*)&H;
        l[2 + j] = *(unsigned*)&L;
    }
    hi = make_uint4(h[0], h[1], h[2], h[3]);
    lo = make_uint4(l[0], l[1], l[2], l[3]);
}
__device__ __forceinline__ uint4 negbf2x4(uint4 a) {
    return make_uint4(a.x ^ 0x80008000u, a.y ^ 0x80008000u,
                      a.z ^ 0x80008000u, a.w ^ 0x80008000u);
}

// ---------------- scratch (static device globals; no allocation) ----------------
__device__ float g_qkv_r[NTOK * D3];       // 25.2 MB
__device__ float g_qkv_i[NTOK * D3];
__device__ float g_kt_r[BATCH * NHEAD * DHEAD * S_LEN];  // 8.4 MB (rotated K, [b,h,d,s])
__device__ float g_kt_i[BATCH * NHEAD * DHEAD * S_LEN];
__device__ float g_attn_r[NTOK * DMODEL];  // 8.4 MB
__device__ float g_attn_i[NTOK * DMODEL];
__device__ float g_rc[S_LEN * DHEAD];
__device__ float g_rs[S_LEN * DHEAD];

// ---------------- RoPE rotor table ----------------
__global__ void rope_table_kernel() {
    int s = blockIdx.x, d = threadIdx.x;
    float inv = powf(10000.0f, -((float)d) / 64.0f);
    float ang = (float)s * inv;
    g_rc[s * DHEAD + d] = cosf(ang);
    g_rs[s * DHEAD + d] = sinf(ang);
}

// ======= complex GEMM via bf16x3 compensated tensor-core mma: C = A * B^T =======
// A:[M,K], B:[N,K] row-major.  re = Ar*Br - Ai*Bi ; im = Ar*Bi + Ai*Br.
// Each fp32 operand split X = XH + XL (bf16 each); X*Y ~= XH*YH + XH*YL + XL*YH.
// Block 128 thr (4 warps 2x2), tile 64x64, BK=16, m16n8k16 MMAs.
#define SSTW 12   // smem row stride in 32-bit words (8 payload + 4 pad): conflict-free
__global__ __launch_bounds__(128)
void cgemm_mma_kernel(const float* __restrict__ Ar, const float* __restrict__ Ai,
                      const float* __restrict__ Br, const float* __restrict__ Bi,
                      float* __restrict__ Cr, float* __restrict__ Ci,
                      int N, int K)
{
    __shared__ unsigned sArH[64 * SSTW], sArL[64 * SSTW];
    __shared__ unsigned sAiH[64 * SSTW], sAiL[64 * SSTW];
    __shared__ unsigned sBrH[64 * SSTW], sBrL[64 * SSTW];
    __shared__ unsigned sBiH[64 * SSTW], sBiL[64 * SSTW];
    __shared__ unsigned sBnH[64 * SSTW], sBnL[64 * SSTW];   // -Bi

    int tid  = threadIdx.x;
    int lane = tid & 31, warp = tid >> 5;
    int wm = (warp & 1) * 32;   // warp m-offset in tile
    int wn = (warp >> 1) * 32;  // warp n-offset
    int g = lane >> 2, t = lane & 3;
    int m0 = blockIdx.y * 64;
    int n0 = blockIdx.x * 64;

    // loader: thread covers row tid>>1, float cols (tid&1)*8 .. +7
    int lrow = tid >> 1;
    int lcol = (tid & 1) * 8;
    int sofs = lrow * SSTW + (tid & 1) * 4;   // word offset of the 4 packed words
    const float* pa_r = Ar + (size_t)(m0 + lrow) * K + lcol;
    const float* pa_i = Ai + (size_t)(m0 + lrow) * K + lcol;
    const float* pb_r = Br + (size_t)(n0 + lrow) * K + lcol;
    const float* pb_i = Bi + (size_t)(n0 + lrow) * K + lcol;

    float acc_r[8][4], acc_i[8][4];
#pragma unroll
    for (int p = 0; p < 8; p++)
#pragma unroll
        for (int j = 0; j < 4; j++) { acc_r[p][j] = 0.f; acc_i[p][j] = 0.f; }

    for (int k0 = 0; k0 < K; k0 += 16) {
        // global loads issued early (overlap previous tile's MMA phase)
        float4 ar0 = *(const float4*)(pa_r + k0);
        float4 ar1 = *(const float4*)(pa_r + k0 + 4);
        float4 ai0 = *(const float4*)(pa_i + k0);
        float4 ai1 = *(const float4*)(pa_i + k0 + 4);
        float4 br0 = *(const float4*)(pb_r + k0);
        float4 br1 = *(const float4*)(pb_r + k0 + 4);
        float4 bi0 = *(const float4*)(pb_i + k0);
        float4 bi1 = *(const float4*)(pb_i + k0 + 4);

        __syncthreads();   // previous iter's frag reads done

        uint4 hi, lo;
        split8(ar0, ar1, hi, lo);
        *(uint4*)(sArH + sofs) = hi;  *(uint4*)(sArL + sofs) = lo;
        split8(ai0, ai1, hi, lo);
        *(uint4*)(sAiH + sofs) = hi;  *(uint4*)(sAiL + sofs) = lo;
        split8(br0, br1, hi, lo);
        *(uint4*)(sBrH + sofs) = hi;  *(uint4*)(sBrL + sofs) = lo;
        split8(bi0, bi1, hi, lo);
        *(uint4*)(sBiH + sofs) = hi;  *(uint4*)(sBiL + sofs) = lo;
        *(uint4*)(sBnH + sofs) = negbf2x4(hi);
        *(uint4*)(sBnL + sofs) = negbf2x4(lo);

        __syncthreads();

        // A fragments (m16n8k16 row-major): a0=(g,t) a1=(g+8,t) a2=(g,t+4) a3=(g+8,t+4)
        unsigned fArH[2][4], fArL[2][4], fAiH[2][4], fAiL[2][4];
#pragma unroll
        for (int mt = 0; mt < 2; mt++) {
            int r0 = (wm + mt * 16 + g) * SSTW + t;
            int r1 = (wm + mt * 16 + g + 8) * SSTW + t;
            fArH[mt][0] = sArH[r0]; fArH[mt][1] = sArH[r1];
            fArH[mt][2] = sArH[r0 + 4]; fArH[mt][3] = sArH[r1 + 4];
            fArL[mt][0] = sArL[r0]; fArL[mt][1] = sArL[r1];
            fArL[mt][2] = sArL[r0 + 4]; fArL[mt][3] = sArL[r1 + 4];
            fAiH[mt][0] = sAiH[r0]; fAiH[mt][1] = sAiH[r1];
            fAiH[mt][2] = sAiH[r0 + 4]; fAiH[mt][3] = sAiH[r1 + 4];
            fAiL[mt][0] = sAiL[r0]; fAiL[mt][1] = sAiL[r1];
            fAiL[mt][2] = sAiL[r0 + 4]; fAiL[mt][3] = sAiL[r1 + 4];
        }

#pragma unroll
        for (int nt = 0; nt < 4; nt++) {
            int rb = (wn + nt * 8 + g) * SSTW + t;
            unsigned brH[2] = {sBrH[rb], sBrH[rb + 4]};
            unsigned brL[2] = {sBrL[rb], sBrL[rb + 4]};
            unsigned biH[2] = {sBiH[rb], sBiH[rb + 4]};
            unsigned biL[2] = {sBiL[rb], sBiL[rb + 4]};
            unsigned bnH[2] = {sBnH[rb], sBnH[rb + 4]};
            unsigned bnL[2] = {sBnL[rb], sBnL[rb + 4]};
#pragma unroll
            for (int mt = 0; mt < 2; mt++) {
                int p = mt * 4 + nt;
                // re += Ar*Br (3-term) + Ai*(-Bi) (3-term)
                mma_bf16(acc_r[p], fArH[mt], brH);
                mma_bf16(acc_r[p], fArH[mt], brL);
                mma_bf16(acc_r[p], fArL[mt], brH);
                mma_bf16(acc_r[p], fAiH[mt], bnH);
                mma_bf16(acc_r[p], fAiH[mt], bnL);
                mma_bf16(acc_r[p], fAiL[mt], bnH);
                // im += Ar*Bi (3-term) + Ai*Br (3-term)
                mma_bf16(acc_i[p], fArH[mt], biH);
                mma_bf16(acc_i[p], fArH[mt], biL);
                mma_bf16(acc_i[p], fArL[mt], biH);
                mma_bf16(acc_i[p], fAiH[mt], brH);
                mma_bf16(acc_i[p], fAiH[mt], brL);
                mma_bf16(acc_i[p], fAiL[mt], brH);
            }
        }
    }

    // epilogue: c0,c1 -> row g cols 2t,2t+1 ; c2,c3 -> row g+8
#pragma unroll
    for (int mt = 0; mt < 2; mt++)
#pragma unroll
        for (int nt = 0; nt < 4; nt++) {
            int p = mt * 4 + nt;
            int m = m0 + wm + mt * 16 + g;
            int n = n0 + wn + nt * 8 + t * 2;
            size_t c0 = (size_t)m * N + n;
            size_t c1 = (size_t)(m + 8) * N + n;
            *(float2*)(Cr + c0) = make_float2(acc_r[p][0], acc_r[p][1]);
            *(float2*)(Cr + c1) = make_float2(acc_r[p][2], acc_r[p][3]);
            *(float2*)(Ci + c0) = make_float2(acc_i[p][0], acc_i[p][1]);
            *(float2*)(Ci + c1) = make_float2(acc_i[p][2], acc_i[p][3]);
        }
}

// ---------- K: rotate + transpose into Kt[b,h,d,s] (coalesced both sides) ------
__global__ __launch_bounds__(256)
void kpack_kernel(const float* __restrict__ qkv_r, const float* __restrict__ qkv_i,
                  float* __restrict__ kt_r, float* __restrict__ kt_i)
{
    __shared__ float Tr[32][33], Ti[32][33];
    int s0 = blockIdx.x * 32;
    int h  = blockIdx.y >> 1;
    int d0 = (blockIdx.y & 1) * 32;
    int b  = blockIdx.z;
    int tid = threadIdx.x;
    int tx = tid & 31, ty = tid >> 5;
    size_t tok = (size_t)b * S_LEN;

#pragma unroll
    for (int r = 0; r < 4; r++) {
        int sl = ty + r * 8;
        int s = s0 + sl;
        int d = d0 + tx;
        size_t off = (tok + s) * D3 + DMODEL + (size_t)h * DHEAD + d;
        float kr = qkv_r[off], ki = qkv_i[off];
        float co = g_rc[s * DHEAD + d], si = g_rs[s * DHEAD + d];
        Tr[sl][tx] = kr * co - ki * si;
        Ti[sl][tx] = kr * si + ki * co;
    }
    __syncthreads();

    size_t base = ((size_t)(b * NHEAD + h) * DHEAD + d0) * S_LEN + s0;
#pragma unroll
    for (int r = 0; r < 4; r++) {
        int dl = ty + r * 8;
        kt_r[base + (size_t)dl * S_LEN + tx] = Tr[tx][dl];
        kt_i[base + (size_t)dl * S_LEN + tx] = Ti[tx][dl];
    }
}

// ---------------- fused attention: one block per (b, h, 16-q tile) ----------------
// dynamic smem: sQr2[16][64] u64 | sQi2[16][64] u64 | sWc[16][512] f | sWs[16][512] f
#define ATTN_SMEM (QB * DHEAD * 8 * 2 + QB * S_LEN * 4 * 2)   // 81920
__global__ __launch_bounds__(256)
void attn_kernel(const float* __restrict__ qkv_r, const float* __restrict__ qkv_i,
                 const float* __restrict__ kt_r, const float* __restrict__ kt_i,
                 float* __restrict__ out_r, float* __restrict__ out_i)
{
    extern __shared__ char smem[];
    u64 (*sQr2)[DHEAD] = (u64(*)[DHEAD])(smem);
    u64 (*sQi2)[DHEAD] = (u64(*)[DHEAD])(smem + QB * DHEAD * 8);
    float (*sWc)[S_LEN] = (float(*)[S_LEN])(smem + QB * DHEAD * 16);
    float (*sWs)[S_LEN] = (float(*)[S_LEN])(smem + QB * DHEAD * 16 + QB * S_LEN * 4);

    int tid = threadIdx.x;
    int h = blockIdx.y, b = blockIdx.z;
    int q0 = blockIdx.x * QB;
    const size_t tok_base = (size_t)b * S_LEN;

    // ---- load + rotate QB Q rows, store pre-dup'd ----
    for (int idx = tid; idx < QB * DHEAD; idx += 256) {
        int q = idx >> 6, d = idx & 63;
        int s = q0 + q;
        size_t off = (tok_base + s) * D3 + (size_t)h * DHEAD + d;
        float qr = qkv_r[off], qi = qkv_i[off];
        float co = g_rc[s * DHEAD + d], si = g_rs[s * DHEAD + d];
        sQr2[q][d] = dup2(qr * co - qi * si);
        sQi2[q][d] = dup2(qr * si + qi * co);
    }
    __syncthreads();

    // ---- scores: thread t handles k-pair (2t, 2t+1) for all QB q ----
    const float scale = 0.125f;  // 1/sqrt(64)
    {
        size_t kt_base = (size_t)(b * NHEAD + h) * DHEAD * S_LEN + 2 * tid;
        const float* pkr = kt_r + kt_base;
        const float* pki = kt_i + kt_base;
        u64 re2[QB], im2[QB];
#pragma unroll
        for (int q = 0; q < QB; q++) { re2[q] = 0ull; im2[q] = 0ull; }
#pragma unroll 2
        for (int d = 0; d < DHEAD; d++) {
            u64 kr = *(const u64*)(pkr + (size_t)d * S_LEN);
            u64 ki = *(const u64*)(pki + (size_t)d * S_LEN);
#pragma unroll
            for (int q = 0; q < QB; q++) {
                u64 qr2 = sQr2[q][d];
                u64 qi2 = sQi2[q][d];
                re2[q] = fma2(qr2, kr, re2[q]);       // + Qr*Kr
                re2[q] = fma2(qi2, ki, re2[q]);       // + Qi*Ki
                im2[q] = fma2(qi2, kr, im2[q]);       // + Qi*Kr
                im2[q] = fma2(neg2(qr2), ki, im2[q]); // - Qr*Ki
            }
        }
#pragma unroll
        for (int q = 0; q < QB; q++) {
            *(float2*)&sWc[q][2 * tid] = make_float2(lo2(re2[q]) * scale, hi2(re2[q]) * scale);
            *(float2*)&sWs[q][2 * tid] = make_float2(lo2(im2[q]) * scale, hi2(im2[q]) * scale);
        }
    }
    __syncthreads();

    // ---- softmax + complex weights: warp w owns q-rows w and w+8 ----
    int w = tid >> 5, l = tid & 31;
#pragma unroll
    for (int rr = 0; rr < 2; rr++) {
        int row = w + rr * 8;
        float mx = -1e30f;
#pragma unroll
        for (int j = 0; j < 16; j++) mx = fmaxf(mx, sWc[row][l + 32 * j]);
#pragma unroll
        for (int o = 16; o > 0; o >>= 1)
            mx = fmaxf(mx, __shfl_xor_sync(0xffffffff, mx, o));

        float sum = 0.f;
#pragma unroll
        for (int j = 0; j < 16; j++) {
            int idx = l + 32 * j;
            float e = __expf(sWc[row][idx] - mx);
            sWc[row][idx] = e;
            sum += e;
        }
#pragma unroll
        for (int o = 16; o > 0; o >>= 1)
            sum += __shfl_xor_sync(0xffffffff, sum, o);
        float inv = 1.0f / sum;

#pragma unroll
        for (int j = 0; j < 16; j++) {
            int idx = l + 32 * j;
            float p = sWc[row][idx] * inv;
            float sv, cv;
            sincosf(sWs[row][idx], &sv, &cv);
            sWc[row][idx] = p * cv;
            sWs[row][idx] = p * sv;
        }
    }
    __syncthreads();

    // ---- AV: warp w -> q-rows w and w+8; lane l -> dims (2l, 2l+1) ----
    const float* pvr = qkv_r + tok_base * D3 + 2 * DMODEL + (size_t)h * DHEAD + 2 * l;
    const float* pvi = qkv_i + tok_base * D3 + 2 * DMODEL + (size_t)h * DHEAD + 2 * l;
    u64 aA0 = 0ull, aB0 = 0ull, aC0 = 0ull, aD0 = 0ull;
    u64 aA1 = 0ull, aB1 = 0ull, aC1 = 0ull, aD1 = 0ull;
#pragma unroll 4
    for (int k = 0; k < S_LEN; k++) {
        u64 vr = *(const u64*)(pvr + (size_t)k * D3);
        u64 vi = *(const u64*)(pvi + (size_t)k * D3);
        u64 wc0 = dup2(sWc[w][k]),     ws0 = dup2(sWs[w][k]);
        u64 wc1 = dup2(sWc[w + 8][k]), ws1 = dup2(sWs[w + 8][k]);
        aA0 = fma2(wc0, vr, aA0);  aB0 = fma2(ws0, vi, aB0);
        aC0 = fma2(wc0, vi, aC0);  aD0 = fma2(ws0, vr, aD0);
        aA1 = fma2(wc1, vr, aA1);  aB1 = fma2(ws1, vi, aB1);
        aC1 = fma2(wc1, vi, aC1);  aD1 = fma2(ws1, vr, aD1);
    }
    size_t o0 = (tok_base + q0 + w) * DMODEL + (size_t)h * DHEAD + 2 * l;
    size_t o1 = (tok_base + q0 + w + 8) * DMODEL + (size_t)h * DHEAD + 2 * l;
    *(float2*)(out_r + o0) = make_float2(lo2(aA0) - lo2(aB0), hi2(aA0) - hi2(aB0));
    *(float2*)(out_i + o0) = make_float2(lo2(aC0) + lo2(aD0), hi2(aC0) + hi2(aD0));
    *(float2*)(out_r + o1) = make_float2(lo2(aA1) - lo2(aB1), hi2(aA1) - hi2(aB1));
    *(float2*)(out_i + o1) = make_float2(lo2(aC1) + lo2(aD1), hi2(aC1) + hi2(aD1));
}

// ---------------- launch ----------------
extern "C" void kernel_launch(void* const* d_in, const int* in_sizes, int n_in,
                              void* d_out, int out_size)
{
    const float* x_re    = (const float*)d_in[0];
    const float* x_im    = (const float*)d_in[1];
    const float* wqkv_re = (const float*)d_in[2];
    const float* wqkv_im = (const float*)d_in[3];
    const float* wo_re   = (const float*)d_in[4];
    const float* wo_im   = (const float*)d_in[5];
    float* out = (float*)d_out;

    float *qkv_r, *qkv_i, *kt_r, *kt_i, *attn_r, *attn_i;
    cudaGetSymbolAddress((void**)&qkv_r,  g_qkv_r);
    cudaGetSymbolAddress((void**)&qkv_i,  g_qkv_i);
    cudaGetSymbolAddress((void**)&kt_r,   g_kt_r);
    cudaGetSymbolAddress((void**)&kt_i,   g_kt_i);
    cudaGetSymbolAddress((void**)&attn_r, g_attn_r);
    cudaGetSymbolAddress((void**)&attn_i, g_attn_i);

    cudaFuncSetAttribute(attn_kernel,
                         cudaFuncAttributeMaxDynamicSharedMemorySize, ATTN_SMEM);

    // 1. RoPE rotor table
    rope_table_kernel<<<S_LEN, DHEAD>>>();

    // 2. complex QKV projection (bf16x3 compensated tensor cores)
    dim3 g1(D3 / 64, NTOK / 64);
    cgemm_mma_kernel<<<g1, 128>>>(x_re, x_im, wqkv_re, wqkv_im, qkv_r, qkv_i, D3, DMODEL);

    // 3. K: rotate + transpose into [b,h,d,s]
    dim3 g2(S_LEN / 32, NHEAD * 2, BATCH);
    kpack_kernel<<<g2, 256>>>(qkv_r, qkv_i, kt_r, kt_i);

    // 4. fused attention, 16 q-rows per block (Q rotated on load)
    dim3 g3(S_LEN / QB, NHEAD, BATCH);
    attn_kernel<<<g3, 256, ATTN_SMEM>>>(qkv_r, qkv_i, kt_r, kt_i, attn_r, attn_i);

    // 5. complex output projection straight into d_out ([2,B,S,D])
    dim3 g4(DMODEL / 64, NTOK / 64);
    cgemm_mma_kernel<<<g4, 128>>>(attn_r, attn_i, wo_re, wo_im,
                                  out, out + (size_t)NTOK * DMODEL, DMODEL, DMODEL);
}

// round 9
// speedup vs baseline: 5.1814x; 1.2895x over previous
#include <cuda_runtime.h>
#include <cuda_bf16.h>
#include <math.h>

#define S_LEN  512
#define BATCH  4
#define NHEAD  16
#define BH     (BATCH * NHEAD)
#define DHEAD  64
#define DMODEL 1024
#define D3     3072
#define NTOK   2048   // BATCH * S_LEN

typedef unsigned long long u64;

// ---------------- bf16 mma helper (m16n8k16, verified layout) ----------------
__device__ __forceinline__ void mma_bf16(float* c, const unsigned* a, const unsigned* b) {
    asm volatile("mma.sync.aligned.m16n8k16.row.col.f32.bf16.bf16.f32 "
        "{%0,%1,%2,%3}, {%4,%5,%6,%7}, {%8,%9}, {%0,%1,%2,%3};"
        : "+f"(c[0]), "+f"(c[1]), "+f"(c[2]), "+f"(c[3])
        : "r"(a[0]), "r"(a[1]), "r"(a[2]), "r"(a[3]), "r"(b[0]), "r"(b[1]));
}

// split fp32 pair (a,b) into packed bf16 hi word + bf16 lo (residual) word
__device__ __forceinline__ void split_pair(float a, float b, unsigned& H, unsigned& L) {
    __nv_bfloat162 h2 = __floats2bfloat162_rn(a, b);
    float ra = a - __bfloat162float(h2.x);
    float rb = b - __bfloat162float(h2.y);
    __nv_bfloat162 l2 = __floats2bfloat162_rn(ra, rb);
    H = *(unsigned*)&h2;
    L = *(unsigned*)&l2;
}

// split 8 consecutive floats into bf16-hi / bf16-lo pair-packed words
__device__ __forceinline__ void split8(const float4& x, const float4& y,
                                       uint4& hi, uint4& lo) {
    unsigned h[4], l[4];
    split_pair(x.x, x.y, h[0], l[0]);
    split_pair(x.z, x.w, h[1], l[1]);
    split_pair(y.x, y.y, h[2], l[2]);
    split_pair(y.z, y.w, h[3], l[3]);
    hi = make_uint4(h[0], h[1], h[2], h[3]);
    lo = make_uint4(l[0], l[1], l[2], l[3]);
}
__device__ __forceinline__ uint4 negbf2x4(uint4 a) {
    return make_uint4(a.x ^ 0x80008000u, a.y ^ 0x80008000u,
                      a.z ^ 0x80008000u, a.w ^ 0x80008000u);
}

// ---------------- scratch (static device globals; no allocation) ----------------
__device__ float g_qkv_r[NTOK * D3];       // 25.2 MB
__device__ float g_qkv_i[NTOK * D3];
__device__ float g_attn_r[NTOK * DMODEL];  // 8.4 MB
__device__ float g_attn_i[NTOK * DMODEL];
__device__ float g_rc[S_LEN * DHEAD];
__device__ float g_rs[S_LEN * DHEAD];
// rotated K, bf16 H/L packed pairs, layout [bh][s][d-pair word] (B-frag ready)
__device__ unsigned g_kbrH[BH * 512 * 32];
__device__ unsigned g_kbrL[BH * 512 * 32];
__device__ unsigned g_kbiH[BH * 512 * 32];
__device__ unsigned g_kbiL[BH * 512 * 32];
// V transposed, bf16 H/L packed pairs, layout [bh][d][s-pair word] (B-frag ready)
__device__ unsigned g_vtrH[BH * 64 * 256];
__device__ unsigned g_vtrL[BH * 64 * 256];
__device__ unsigned g_vtiH[BH * 64 * 256];
__device__ unsigned g_vtiL[BH * 64 * 256];

// ---------------- RoPE rotor table ----------------
__global__ void rope_table_kernel() {
    int s = blockIdx.x, d = threadIdx.x;
    float inv = powf(10000.0f, -((float)d) / 64.0f);
    float ang = (float)s * inv;
    g_rc[s * DHEAD + d] = cosf(ang);
    g_rs[s * DHEAD + d] = sinf(ang);
}

// ======= complex GEMM via bf16x3 compensated tensor-core mma: C = A * B^T =======
#define SSTW 12
__global__ __launch_bounds__(128)
void cgemm_mma_kernel(const float* __restrict__ Ar, const float* __restrict__ Ai,
                      const float* __restrict__ Br, const float* __restrict__ Bi,
                      float* __restrict__ Cr, float* __restrict__ Ci,
                      int N, int K)
{
    __shared__ unsigned sArH[64 * SSTW], sArL[64 * SSTW];
    __shared__ unsigned sAiH[64 * SSTW], sAiL[64 * SSTW];
    __shared__ unsigned sBrH[64 * SSTW], sBrL[64 * SSTW];
    __shared__ unsigned sBiH[64 * SSTW], sBiL[64 * SSTW];
    __shared__ unsigned sBnH[64 * SSTW], sBnL[64 * SSTW];   // -Bi

    int tid  = threadIdx.x;
    int lane = tid & 31, warp = tid >> 5;
    int wm = (warp & 1) * 32;
    int wn = (warp >> 1) * 32;
    int g = lane >> 2, t = lane & 3;
    int m0 = blockIdx.y * 64;
    int n0 = blockIdx.x * 64;

    int lrow = tid >> 1;
    int lcol = (tid & 1) * 8;
    int sofs = lrow * SSTW + (tid & 1) * 4;
    const float* pa_r = Ar + (size_t)(m0 + lrow) * K + lcol;
    const float* pa_i = Ai + (size_t)(m0 + lrow) * K + lcol;
    const float* pb_r = Br + (size_t)(n0 + lrow) * K + lcol;
    const float* pb_i = Bi + (size_t)(n0 + lrow) * K + lcol;

    float acc_r[8][4], acc_i[8][4];
#pragma unroll
    for (int p = 0; p < 8; p++)
#pragma unroll
        for (int j = 0; j < 4; j++) { acc_r[p][j] = 0.f; acc_i[p][j] = 0.f; }

    for (int k0 = 0; k0 < K; k0 += 16) {
        float4 ar0 = *(const float4*)(pa_r + k0);
        float4 ar1 = *(const float4*)(pa_r + k0 + 4);
        float4 ai0 = *(const float4*)(pa_i + k0);
        float4 ai1 = *(const float4*)(pa_i + k0 + 4);
        float4 br0 = *(const float4*)(pb_r + k0);
        float4 br1 = *(const float4*)(pb_r + k0 + 4);
        float4 bi0 = *(const float4*)(pb_i + k0);
        float4 bi1 = *(const float4*)(pb_i + k0 + 4);

        __syncthreads();

        uint4 hi, lo;
        split8(ar0, ar1, hi, lo);
        *(uint4*)(sArH + sofs) = hi;  *(uint4*)(sArL + sofs) = lo;
        split8(ai0, ai1, hi, lo);
        *(uint4*)(sAiH + sofs) = hi;  *(uint4*)(sAiL + sofs) = lo;
        split8(br0, br1, hi, lo);
        *(uint4*)(sBrH + sofs) = hi;  *(uint4*)(sBrL + sofs) = lo;
        split8(bi0, bi1, hi, lo);
        *(uint4*)(sBiH + sofs) = hi;  *(uint4*)(sBiL + sofs) = lo;
        *(uint4*)(sBnH + sofs) = negbf2x4(hi);
        *(uint4*)(sBnL + sofs) = negbf2x4(lo);

        __syncthreads();

        unsigned fArH[2][4], fArL[2][4], fAiH[2][4], fAiL[2][4];
#pragma unroll
        for (int mt = 0; mt < 2; mt++) {
            int r0 = (wm + mt * 16 + g) * SSTW + t;
            int r1 = (wm + mt * 16 + g + 8) * SSTW + t;
            fArH[mt][0] = sArH[r0]; fArH[mt][1] = sArH[r1];
            fArH[mt][2] = sArH[r0 + 4]; fArH[mt][3] = sArH[r1 + 4];
            fArL[mt][0] = sArL[r0]; fArL[mt][1] = sArL[r1];
            fArL[mt][2] = sArL[r0 + 4]; fArL[mt][3] = sArL[r1 + 4];
            fAiH[mt][0] = sAiH[r0]; fAiH[mt][1] = sAiH[r1];
            fAiH[mt][2] = sAiH[r0 + 4]; fAiH[mt][3] = sAiH[r1 + 4];
            fAiL[mt][0] = sAiL[r0]; fAiL[mt][1] = sAiL[r1];
            fAiL[mt][2] = sAiL[r0 + 4]; fAiL[mt][3] = sAiL[r1 + 4];
        }

#pragma unroll
        for (int nt = 0; nt < 4; nt++) {
            int rb = (wn + nt * 8 + g) * SSTW + t;
            unsigned brH[2] = {sBrH[rb], sBrH[rb + 4]};
            unsigned brL[2] = {sBrL[rb], sBrL[rb + 4]};
            unsigned biH[2] = {sBiH[rb], sBiH[rb + 4]};
            unsigned biL[2] = {sBiL[rb], sBiL[rb + 4]};
            unsigned bnH[2] = {sBnH[rb], sBnH[rb + 4]};
            unsigned bnL[2] = {sBnL[rb], sBnL[rb + 4]};
#pragma unroll
            for (int mt = 0; mt < 2; mt++) {
                int p = mt * 4 + nt;
                mma_bf16(acc_r[p], fArH[mt], brH);
                mma_bf16(acc_r[p], fArH[mt], brL);
                mma_bf16(acc_r[p], fArL[mt], brH);
                mma_bf16(acc_r[p], fAiH[mt], bnH);
                mma_bf16(acc_r[p], fAiH[mt], bnL);
                mma_bf16(acc_r[p], fAiL[mt], bnH);
                mma_bf16(acc_i[p], fArH[mt], biH);
                mma_bf16(acc_i[p], fArH[mt], biL);
                mma_bf16(acc_i[p], fArL[mt], biH);
                mma_bf16(acc_i[p], fAiH[mt], brH);
                mma_bf16(acc_i[p], fAiH[mt], brL);
                mma_bf16(acc_i[p], fAiL[mt], brH);
            }
        }
    }

#pragma unroll
    for (int mt = 0; mt < 2; mt++)
#pragma unroll
        for (int nt = 0; nt < 4; nt++) {
            int p = mt * 4 + nt;
            int m = m0 + wm + mt * 16 + g;
            int n = n0 + wn + nt * 8 + t * 2;
            size_t c0 = (size_t)m * N + n;
            size_t c1 = (size_t)(m + 8) * N + n;
            *(float2*)(Cr + c0) = make_float2(acc_r[p][0], acc_r[p][1]);
            *(float2*)(Cr + c1) = make_float2(acc_r[p][2], acc_r[p][3]);
            *(float2*)(Ci + c0) = make_float2(acc_i[p][0], acc_i[p][1]);
            *(float2*)(Ci + c1) = make_float2(acc_i[p][2], acc_i[p][3]);
        }
}

// ---------- K: rotate + split to bf16 H/L pairs, layout [bh][s][d-pair] ----------
__global__ __launch_bounds__(256)
void kpack_kernel(const float* __restrict__ qkv_r, const float* __restrict__ qkv_i)
{
    int bh = blockIdx.y;
    int b = bh >> 4, h = bh & 15;
    int id = blockIdx.x * 256 + threadIdx.x;   // 0..16383 = s*32 + wd
    int s = id >> 5, wd = id & 31;
    int d = 2 * wd;
    size_t off = ((size_t)b * S_LEN + s) * D3 + DMODEL + (size_t)h * DHEAD + d;
    float2 kr = *(const float2*)(qkv_r + off);
    float2 ki = *(const float2*)(qkv_i + off);
    float2 co = *(const float2*)(g_rc + s * DHEAD + d);
    float2 si = *(const float2*)(g_rs + s * DHEAD + d);
    float r0 = kr.x * co.x - ki.x * si.x;
    float i0 = kr.x * si.x + ki.x * co.x;
    float r1 = kr.y * co.y - ki.y * si.y;
    float i1 = kr.y * si.y + ki.y * co.y;
    size_t o = (size_t)bh * 16384 + id;
    unsigned H, L;
    split_pair(r0, r1, H, L); g_kbrH[o] = H; g_kbrL[o] = L;
    split_pair(i0, i1, H, L); g_kbiH[o] = H; g_kbiL[o] = L;
}

// ---------- V: transpose + split to bf16 H/L pairs, layout [bh][d][s-pair] ----------
__global__ __launch_bounds__(256)
void vpack_kernel(const float* __restrict__ qkv_r, const float* __restrict__ qkv_i)
{
    __shared__ float sVr[64][65], sVi[64][65];
    int sc = blockIdx.x;       // s-chunk of 64
    int bh = blockIdx.y;
    int b = bh >> 4, h = bh & 15;
    int tid = threadIdx.x;

#pragma unroll
    for (int i = 0; i < 16; i++) {
        int id = i * 256 + tid;        // 0..4095 = sl*64 + d
        int sl = id >> 6, d = id & 63;
        size_t off = ((size_t)b * S_LEN + sc * 64 + sl) * D3 + 2 * DMODEL
                   + (size_t)h * DHEAD + d;
        sVr[sl][d] = qkv_r[off];
        sVi[sl][d] = qkv_i[off];
    }
    __syncthreads();

#pragma unroll
    for (int i = 0; i < 8; i++) {
        int id = i * 256 + tid;        // 0..2047 = d*32 + ws
        int d = id >> 5, ws = id & 31;
        size_t o = ((size_t)bh * 64 + d) * 256 + sc * 32 + ws;
        unsigned H, L;
        split_pair(sVr[2 * ws][d], sVr[2 * ws + 1][d], H, L);
        g_vtrH[o] = H; g_vtrL[o] = L;
        split_pair(sVi[2 * ws][d], sVi[2 * ws + 1][d], H, L);
        g_vtiH[o] = H; g_vtiL[o] = L;
    }
}

// ========== fused attention, all-MMA: one block per (b, h, 16-q tile) ==========
// smem word layout:
//   sQ{rH,rL,iH,iL}: [16][36]  (frag stride 36 -> bank 4g+t, conflict-free)
//   sWc, sWs (fp32): [16][514]
//   sW{cH,cL,sH,sL}: [16][260] bf16 pair words
#define OFF_QRH 0
#define OFF_QRL 576
#define OFF_QIH 1152
#define OFF_QIL 1728
#define OFF_WC  2304
#define OFF_WS  10528
#define OFF_WCH 18752
#define OFF_WCL 22912
#define OFF_WSH 27072
#define OFF_WSL 31232
#define ATTN_SMEM_WORDS 35392
#define ATTN_SMEM (ATTN_SMEM_WORDS * 4)

__global__ __launch_bounds__(256)
void attn_kernel(const float* __restrict__ qkv_r, const float* __restrict__ qkv_i,
                 float* __restrict__ out_r, float* __restrict__ out_i)
{
    extern __shared__ unsigned sm[];
    unsigned* sQrH = sm + OFF_QRH;
    unsigned* sQrL = sm + OFF_QRL;
    unsigned* sQiH = sm + OFF_QIH;
    unsigned* sQiL = sm + OFF_QIL;
    float* sWc = (float*)(sm + OFF_WC);
    float* sWs = (float*)(sm + OFF_WS);
    unsigned* sWcH = sm + OFF_WCH;
    unsigned* sWcL = sm + OFF_WCL;
    unsigned* sWsH = sm + OFF_WSH;
    unsigned* sWsL = sm + OFF_WSL;

    int tid = threadIdx.x;
    int w = tid >> 5, l = tid & 31;
    int g = l >> 2, t = l & 3;
    int h = blockIdx.y, b = blockIdx.z;
    int bh = b * NHEAD + h;
    int q0 = blockIdx.x * 16;
    const size_t tok = (size_t)b * S_LEN;

    // ---- Q: load + rotate + split, word layout [q][d-pair] stride 36 ----
#pragma unroll
    for (int i = 0; i < 2; i++) {
        int id = tid + 256 * i;        // 0..511 = q*32 + wd
        int q = id >> 5, wd = id & 31;
        int s = q0 + q;
        int d = 2 * wd;
        size_t off = (tok + s) * D3 + (size_t)h * DHEAD + d;
        float2 qr = *(const float2*)(qkv_r + off);
        float2 qi = *(const float2*)(qkv_i + off);
        float2 co = *(const float2*)(g_rc + s * DHEAD + d);
        float2 si = *(const float2*)(g_rs + s * DHEAD + d);
        float r0 = qr.x * co.x - qi.x * si.x;
        float i0 = qr.x * si.x + qi.x * co.x;
        float r1 = qr.y * co.y - qi.y * si.y;
        float i1 = qr.y * si.y + qi.y * co.y;
        unsigned H, L;
        split_pair(r0, r1, H, L); sQrH[q * 36 + wd] = H; sQrL[q * 36 + wd] = L;
        split_pair(i0, i1, H, L); sQiH[q * 36 + wd] = H; sQiL[q * 36 + wd] = L;
    }
    __syncthreads();

    // ---- scores MMA: warp w owns k-rows [64w, 64w+64) ----
    {
        float accR[8][4], accI[8][4];
#pragma unroll
        for (int p = 0; p < 8; p++)
#pragma unroll
            for (int j = 0; j < 4; j++) { accR[p][j] = 0.f; accI[p][j] = 0.f; }

        const size_t kbase = (size_t)bh * 16384;
#pragma unroll
        for (int ks = 0; ks < 4; ks++) {
            int r0 = g * 36 + ks * 8 + t;
            int r1 = (g + 8) * 36 + ks * 8 + t;
            unsigned aQrH[4] = {sQrH[r0], sQrH[r1], sQrH[r0 + 4], sQrH[r1 + 4]};
            unsigned aQrL[4] = {sQrL[r0], sQrL[r1], sQrL[r0 + 4], sQrL[r1 + 4]};
            unsigned aQiH[4] = {sQiH[r0], sQiH[r1], sQiH[r0 + 4], sQiH[r1 + 4]};
            unsigned aQiL[4] = {sQiL[r0], sQiL[r1], sQiL[r0 + 4], sQiL[r1 + 4]};
            unsigned nQrH[4], nQrL[4];
#pragma unroll
            for (int j = 0; j < 4; j++) {
                nQrH[j] = aQrH[j] ^ 0x80008000u;
                nQrL[j] = aQrL[j] ^ 0x80008000u;
            }
#pragma unroll
            for (int nt = 0; nt < 8; nt++) {
                int srow = w * 64 + nt * 8 + g;
                size_t kb = kbase + (size_t)srow * 32 + ks * 8 + t;
                unsigned krH[2] = {g_kbrH[kb], g_kbrH[kb + 4]};
                unsigned krL[2] = {g_kbrL[kb], g_kbrL[kb + 4]};
                unsigned kiH[2] = {g_kbiH[kb], g_kbiH[kb + 4]};
                unsigned kiL[2] = {g_kbiL[kb], g_kbiL[kb + 4]};
                // re = Qr*Kr + Qi*Ki  (3-term each)
                mma_bf16(accR[nt], aQrH, krH);
                mma_bf16(accR[nt], aQrH, krL);
                mma_bf16(accR[nt], aQrL, krH);
                mma_bf16(accR[nt], aQiH, kiH);
                mma_bf16(accR[nt], aQiH, kiL);
                mma_bf16(accR[nt], aQiL, kiH);
                // im = Qi*Kr - Qr*Ki  (3-term each, A-side negation)
                mma_bf16(accI[nt], aQiH, krH);
                mma_bf16(accI[nt], aQiH, krL);
                mma_bf16(accI[nt], aQiL, krH);
                mma_bf16(accI[nt], nQrH, kiH);
                mma_bf16(accI[nt], nQrH, kiL);
                mma_bf16(accI[nt], nQrL, kiH);
            }
        }

        const float scale = 0.125f;   // 1/sqrt(64)
#pragma unroll
        for (int nt = 0; nt < 8; nt++) {
            int col = w * 64 + nt * 8 + 2 * t;
            *(float2*)&sWc[g * 514 + col] =
                make_float2(accR[nt][0] * scale, accR[nt][1] * scale);
            *(float2*)&sWc[(g + 8) * 514 + col] =
                make_float2(accR[nt][2] * scale, accR[nt][3] * scale);
            *(float2*)&sWs[g * 514 + col] =
                make_float2(accI[nt][0] * scale, accI[nt][1] * scale);
            *(float2*)&sWs[(g + 8) * 514 + col] =
                make_float2(accI[nt][2] * scale, accI[nt][3] * scale);
        }
    }
    __syncthreads();

    // ---- softmax + complex weights (bf16 H/L split): warp w -> rows w, w+8 ----
#pragma unroll
    for (int rr = 0; rr < 2; rr++) {
        int row = w + rr * 8;
        float* rc_ = sWc + row * 514;
        float* rs_ = sWs + row * 514;

        float mx = -1e30f;
#pragma unroll
        for (int j = 0; j < 16; j++) mx = fmaxf(mx, rc_[l + 32 * j]);
#pragma unroll
        for (int o = 16; o > 0; o >>= 1)
            mx = fmaxf(mx, __shfl_xor_sync(0xffffffff, mx, o));

        float sum = 0.f;
#pragma unroll
        for (int j = 0; j < 16; j++) {
            int idx = l + 32 * j;
            float e = __expf(rc_[idx] - mx);
            rc_[idx] = e;
            sum += e;
        }
#pragma unroll
        for (int o = 16; o > 0; o >>= 1)
            sum += __shfl_xor_sync(0xffffffff, sum, o);
        float inv = 1.0f / sum;

#pragma unroll
        for (int j = 0; j < 8; j++) {
            int k0 = 2 * l + 64 * j;
            int wd = l + 32 * j;
            float p0 = rc_[k0] * inv, p1 = rc_[k0 + 1] * inv;
            float s0, c0, s1, c1;
            sincosf(rs_[k0], &s0, &c0);
            sincosf(rs_[k0 + 1], &s1, &c1);
            unsigned H, L;
            split_pair(p0 * c0, p1 * c1, H, L);
            sWcH[row * 260 + wd] = H; sWcL[row * 260 + wd] = L;
            split_pair(p0 * s0, p1 * s1, H, L);
            sWsH[row * 260 + wd] = H; sWsL[row * 260 + wd] = L;
        }
    }
    __syncthreads();

    // ---- AV MMA: warp w -> d-cols [8w, 8w+8) ----
    {
        float oR[4] = {0.f, 0.f, 0.f, 0.f};
        float oI[4] = {0.f, 0.f, 0.f, 0.f};
        const size_t vbase = ((size_t)bh * 64 + 8 * w + g) * 256;
#pragma unroll 4
        for (int ks = 0; ks < 32; ks++) {
            int r0 = g * 260 + ks * 8 + t;
            int r1 = (g + 8) * 260 + ks * 8 + t;
            unsigned awcH[4] = {sWcH[r0], sWcH[r1], sWcH[r0 + 4], sWcH[r1 + 4]};
            unsigned awcL[4] = {sWcL[r0], sWcL[r1], sWcL[r0 + 4], sWcL[r1 + 4]};
            unsigned awsH[4] = {sWsH[r0], sWsH[r1], sWsH[r0 + 4], sWsH[r1 + 4]};
            unsigned awsL[4] = {sWsL[r0], sWsL[r1], sWsL[r0 + 4], sWsL[r1 + 4]};
            unsigned nwsH[4], nwsL[4];
#pragma unroll
            for (int j = 0; j < 4; j++) {
                nwsH[j] = awsH[j] ^ 0x80008000u;
                nwsL[j] = awsL[j] ^ 0x80008000u;
            }
            size_t vb = vbase + ks * 8 + t;
            unsigned vrH[2] = {g_vtrH[vb], g_vtrH[vb + 4]};
            unsigned vrL[2] = {g_vtrL[vb], g_vtrL[vb + 4]};
            unsigned viH[2] = {g_vtiH[vb], g_vtiH[vb + 4]};
            unsigned viL[2] = {g_vtiL[vb], g_vtiL[vb + 4]};
            // out_r = Wc*Vr - Ws*Vi
            mma_bf16(oR, awcH, vrH);
            mma_bf16(oR, awcH, vrL);
            mma_bf16(oR, awcL, vrH);
            mma_bf16(oR, nwsH, viH);
            mma_bf16(oR, nwsH, viL);
            mma_bf16(oR, nwsL, viH);
            // out_i = Wc*Vi + Ws*Vr
            mma_bf16(oI, awcH, viH);
            mma_bf16(oI, awcH, viL);
            mma_bf16(oI, awcL, viH);
            mma_bf16(oI, awsH, vrH);
            mma_bf16(oI, awsH, vrL);
            mma_bf16(oI, awsL, vrH);
        }
        int dcol = 8 * w + 2 * t;
        size_t o0 = (tok + q0 + g) * DMODEL + (size_t)h * DHEAD + dcol;
        size_t o1 = (tok + q0 + g + 8) * DMODEL + (size_t)h * DHEAD + dcol;
        *(float2*)(out_r + o0) = make_float2(oR[0], oR[1]);
        *(float2*)(out_r + o1) = make_float2(oR[2], oR[3]);
        *(float2*)(out_i + o0) = make_float2(oI[0], oI[1]);
        *(float2*)(out_i + o1) = make_float2(oI[2], oI[3]);
    }
}

// ---------------- launch ----------------
extern "C" void kernel_launch(void* const* d_in, const int* in_sizes, int n_in,
                              void* d_out, int out_size)
{
    const float* x_re    = (const float*)d_in[0];
    const float* x_im    = (const float*)d_in[1];
    const float* wqkv_re = (const float*)d_in[2];
    const float* wqkv_im = (const float*)d_in[3];
    const float* wo_re   = (const float*)d_in[4];
    const float* wo_im   = (const float*)d_in[5];
    float* out = (float*)d_out;

    float *qkv_r, *qkv_i, *attn_r, *attn_i;
    cudaGetSymbolAddress((void**)&qkv_r,  g_qkv_r);
    cudaGetSymbolAddress((void**)&qkv_i,  g_qkv_i);
    cudaGetSymbolAddress((void**)&attn_r, g_attn_r);
    cudaGetSymbolAddress((void**)&attn_i, g_attn_i);

    cudaFuncSetAttribute(attn_kernel,
                         cudaFuncAttributeMaxDynamicSharedMemorySize, ATTN_SMEM);

    // 1. RoPE rotor table
    rope_table_kernel<<<S_LEN, DHEAD>>>();

    // 2. complex QKV projection (bf16x3 compensated tensor cores)
    dim3 g1(D3 / 64, NTOK / 64);
    cgemm_mma_kernel<<<g1, 128>>>(x_re, x_im, wqkv_re, wqkv_im, qkv_r, qkv_i, D3, DMODEL);

    // 3. K rotate+split and V transpose+split into MMA-ready bf16 H/L arrays
    dim3 g2(64, BH);
    kpack_kernel<<<g2, 256>>>(qkv_r, qkv_i);
    dim3 g3(S_LEN / 64, BH);
    vpack_kernel<<<g3, 256>>>(qkv_r, qkv_i);

    // 4. fused all-MMA attention, 16 q-rows per block
    dim3 g4(S_LEN / 16, NHEAD, BATCH);
    attn_kernel<<<g4, 256, ATTN_SMEM>>>(qkv_r, qkv_i, attn_r, attn_i);

    // 5. complex output projection straight into d_out ([2,B,S,D])
    dim3 g5(DMODEL / 64, NTOK / 64);
    cgemm_mma_kernel<<<g5, 128>>>(attn_r, attn_i, wo_re, wo_im,
                                  out, out + (size_t)NTOK * DMODEL, DMODEL, DMODEL);
}